// round 2
// baseline (speedup 1.0000x reference)
#include <cuda_runtime.h>

// LIF spiking neuron: T=4, THRESH=1.0, TAU=1.0.
// x: [T=4, N=8388608] float32, out spikes: same shape float32.
// Per slot: mem += x[t]; spike = (mem > 1); mem = spike ? 0 : mem
// Each thread handles 2 contiguous float4 (8 floats) across all T steps.
// Streaming cache hints (.cs) since there is zero data reuse.

__device__ __forceinline__ float4 ldcs4(const float4* p) {
    return __ldcs(p);
}

__device__ __forceinline__ void step4(float4& mem, const float4& xin, float4& s) {
    mem.x += xin.x; mem.y += xin.y; mem.z += xin.z; mem.w += xin.w;
    s.x = (mem.x > 1.0f) ? 1.0f : 0.0f;
    s.y = (mem.y > 1.0f) ? 1.0f : 0.0f;
    s.z = (mem.z > 1.0f) ? 1.0f : 0.0f;
    s.w = (mem.w > 1.0f) ? 1.0f : 0.0f;
    mem.x = (s.x > 0.f) ? 0.f : mem.x;
    mem.y = (s.y > 0.f) ? 0.f : mem.y;
    mem.z = (s.z > 0.f) ? 0.f : mem.z;
    mem.w = (s.w > 0.f) ? 0.f : mem.w;
}

__global__ void __launch_bounds__(256) lif_spike_kernel(
    const float4* __restrict__ x,
    float4* __restrict__ out,
    int n4)   // number of float4 per timestep (2097152)
{
    // Each thread owns 2 adjacent float4 slots: a = 2*tid, b = 2*tid+1
    int tid = blockIdx.x * blockDim.x + threadIdx.x;
    int ia = 2 * tid;
    int ib = ia + 1;
    if (ib >= n4) {
        if (ia >= n4) return;
        // odd tail (won't happen for this shape, but stay safe)
        float4 mem = make_float4(0.f, 0.f, 0.f, 0.f);
        #pragma unroll
        for (int t = 0; t < 4; t++) {
            float4 xv = __ldcs(x + ia + t * n4);
            float4 s;
            step4(mem, xv, s);
            __stcs(out + ia + t * n4, s);
        }
        return;
    }

    // Front-batch all 8 loads: MLP = 8 per thread.
    float4 xa0 = __ldcs(x + ia);
    float4 xb0 = __ldcs(x + ib);
    float4 xa1 = __ldcs(x + ia + n4);
    float4 xb1 = __ldcs(x + ib + n4);
    float4 xa2 = __ldcs(x + ia + 2 * n4);
    float4 xb2 = __ldcs(x + ib + 2 * n4);
    float4 xa3 = __ldcs(x + ia + 3 * n4);
    float4 xb3 = __ldcs(x + ib + 3 * n4);

    float4 mema = make_float4(0.f, 0.f, 0.f, 0.f);
    float4 memb = make_float4(0.f, 0.f, 0.f, 0.f);
    float4 s;

    step4(mema, xa0, s); __stcs(out + ia, s);
    step4(memb, xb0, s); __stcs(out + ib, s);

    step4(mema, xa1, s); __stcs(out + ia + n4, s);
    step4(memb, xb1, s); __stcs(out + ib + n4, s);

    step4(mema, xa2, s); __stcs(out + ia + 2 * n4, s);
    step4(memb, xb2, s); __stcs(out + ib + 2 * n4, s);

    step4(mema, xa3, s); __stcs(out + ia + 3 * n4, s);
    step4(memb, xb3, s); __stcs(out + ib + 3 * n4, s);
}

extern "C" void kernel_launch(void* const* d_in, const int* in_sizes, int n_in,
                              void* d_out, int out_size)
{
    const float4* x = (const float4*)d_in[0];
    float4* out = (float4*)d_out;

    int total = in_sizes[0];       // T * N floats
    int n_per_t = total / 4;       // floats per timestep
    int n4 = n_per_t / 4;          // float4 per timestep

    int threads = 256;
    int slots_per_block = threads * 2;               // 2 float4 per thread
    int blocks = (n4 + slots_per_block - 1) / slots_per_block;
    lif_spike_kernel<<<blocks, threads>>>(x, out, n4);
}

// round 3
// speedup vs baseline: 1.0478x; 1.0478x over previous
#include <cuda_runtime.h>

// LIF spiking neuron: T=4, THRESH=1.0, TAU=1.0.
// x: [T=4, N=8388608] float32, out spikes: same shape float32.
// Per slot: mem += x[t]; spike = (mem > 1); mem = spike ? 0 : mem
// R1 structure (1 float4 per thread, 32 regs, high occupancy) plus
// streaming cache hints (.cs) — zero reuse, keep L2 churn minimal.

__global__ void __launch_bounds__(256) lif_spike_kernel(
    const float4* __restrict__ x,
    float4* __restrict__ out,
    int n4)   // number of float4 per timestep (2097152)
{
    int i = blockIdx.x * blockDim.x + threadIdx.x;
    if (i >= n4) return;

    // Front-batch the 4 independent timestep loads: MLP = 4.
    float4 x0 = __ldcs(x + i);
    float4 x1 = __ldcs(x + i + n4);
    float4 x2 = __ldcs(x + i + 2 * n4);
    float4 x3 = __ldcs(x + i + 3 * n4);

    float4 mem = make_float4(0.f, 0.f, 0.f, 0.f);
    float4 s;

    // t = 0
    mem.x += x0.x; mem.y += x0.y; mem.z += x0.z; mem.w += x0.w;
    s.x = (mem.x > 1.0f) ? 1.0f : 0.0f;
    s.y = (mem.y > 1.0f) ? 1.0f : 0.0f;
    s.z = (mem.z > 1.0f) ? 1.0f : 0.0f;
    s.w = (mem.w > 1.0f) ? 1.0f : 0.0f;
    __stcs(out + i, s);
    mem.x = (s.x > 0.f) ? 0.f : mem.x;
    mem.y = (s.y > 0.f) ? 0.f : mem.y;
    mem.z = (s.z > 0.f) ? 0.f : mem.z;
    mem.w = (s.w > 0.f) ? 0.f : mem.w;

    // t = 1
    mem.x += x1.x; mem.y += x1.y; mem.z += x1.z; mem.w += x1.w;
    s.x = (mem.x > 1.0f) ? 1.0f : 0.0f;
    s.y = (mem.y > 1.0f) ? 1.0f : 0.0f;
    s.z = (mem.z > 1.0f) ? 1.0f : 0.0f;
    s.w = (mem.w > 1.0f) ? 1.0f : 0.0f;
    __stcs(out + i + n4, s);
    mem.x = (s.x > 0.f) ? 0.f : mem.x;
    mem.y = (s.y > 0.f) ? 0.f : mem.y;
    mem.z = (s.z > 0.f) ? 0.f : mem.z;
    mem.w = (s.w > 0.f) ? 0.f : mem.w;

    // t = 2
    mem.x += x2.x; mem.y += x2.y; mem.z += x2.z; mem.w += x2.w;
    s.x = (mem.x > 1.0f) ? 1.0f : 0.0f;
    s.y = (mem.y > 1.0f) ? 1.0f : 0.0f;
    s.z = (mem.z > 1.0f) ? 1.0f : 0.0f;
    s.w = (mem.w > 1.0f) ? 1.0f : 0.0f;
    __stcs(out + i + 2 * n4, s);
    mem.x = (s.x > 0.f) ? 0.f : mem.x;
    mem.y = (s.y > 0.f) ? 0.f : mem.y;
    mem.z = (s.z > 0.f) ? 0.f : mem.z;
    mem.w = (s.w > 0.f) ? 0.f : mem.w;

    // t = 3 (no membrane update after last spike)
    mem.x += x3.x; mem.y += x3.y; mem.z += x3.z; mem.w += x3.w;
    s.x = (mem.x > 1.0f) ? 1.0f : 0.0f;
    s.y = (mem.y > 1.0f) ? 1.0f : 0.0f;
    s.z = (mem.z > 1.0f) ? 1.0f : 0.0f;
    s.w = (mem.w > 1.0f) ? 1.0f : 0.0f;
    __stcs(out + i + 3 * n4, s);
}

extern "C" void kernel_launch(void* const* d_in, const int* in_sizes, int n_in,
                              void* d_out, int out_size)
{
    const float4* x = (const float4*)d_in[0];
    float4* out = (float4*)d_out;

    int total = in_sizes[0];       // T * N floats
    int n_per_t = total / 4;       // floats per timestep
    int n4 = n_per_t / 4;          // float4 per timestep

    int threads = 256;
    int blocks = (n4 + threads - 1) / threads;
    lif_spike_kernel<<<blocks, threads>>>(x, out, n4);
}